// round 12
// baseline (speedup 1.0000x reference)
#include <cuda_runtime.h>
#include <cuda_fp16.h>
#include <cstdint>

#define NNODES 16384
#define NEDGES 65536
#define MAXF   4096

// ---------------- scratch (device globals; no allocation) ----------------
__device__ __half g_a[(size_t)NNODES * MAXF];     // activation buffer A (fp16)
__device__ __half g_g[(size_t)NNODES * MAXF];     // buffer B (fp16)
__device__ __half g_wt[(size_t)4096 * 4096];      // transposed weights fp16 [Npad,K]
__device__ float g_deg[NNODES];
__device__ float g_dinv[NNODES];
__device__ float g_self[NNODES];
__device__ int   g_count[NNODES];
__device__ int   g_rowptr[NNODES + 1];
__device__ int   g_cursor[NNODES];
__device__ int   g_csrc[NEDGES];
__device__ float g_cw[NEDGES];

// ---------------- PTX helpers (baseline PTX only) ----------------
__device__ __forceinline__ uint32_t smem_u32(const void* p) {
    uint32_t a;
    asm("{ .reg .u64 t; cvta.to.shared.u64 t, %1; cvt.u32.u64 %0, t; }" : "=r"(a) : "l"(p));
    return a;
}
__device__ __forceinline__ void cp16(uint32_t s, const void* g) {
    asm volatile("cp.async.cg.shared.global [%0], [%1], 16;" :: "r"(s), "l"(g));
}
__device__ __forceinline__ void cp_commit() { asm volatile("cp.async.commit_group;" ::: "memory"); }
template <int N>
__device__ __forceinline__ void cp_wait() { asm volatile("cp.async.wait_group %0;" :: "n"(N) : "memory"); }

__device__ __forceinline__ void ldsm4(uint32_t* r, uint32_t addr) {
    asm volatile("ldmatrix.sync.aligned.m8n8.x4.shared.b16 {%0,%1,%2,%3}, [%4];"
                 : "=r"(r[0]), "=r"(r[1]), "=r"(r[2]), "=r"(r[3]) : "r"(addr));
}
__device__ __forceinline__ void mma16816(float* d, const uint32_t* a, const uint32_t* b) {
    asm volatile(
        "mma.sync.aligned.m16n8k16.row.col.f32.f16.f16.f32 "
        "{%0,%1,%2,%3}, {%4,%5,%6,%7}, {%8,%9}, {%0,%1,%2,%3};"
        : "+f"(d[0]), "+f"(d[1]), "+f"(d[2]), "+f"(d[3])
        : "r"(a[0]), "r"(a[1]), "r"(a[2]), "r"(a[3]), "r"(b[0]), "r"(b[1]));
}

// ---------------- graph prep ----------------
__global__ void k_prep_zero() {
    int i = blockIdx.x * blockDim.x + threadIdx.x;
    if (i < NNODES) { g_deg[i] = 0.f; g_count[i] = 0; }
}
__global__ void k_prep_edges(const int* __restrict__ src, const int* __restrict__ dst,
                             const float* __restrict__ ew) {
    int e = blockIdx.x * blockDim.x + threadIdx.x;
    if (e < NEDGES) {
        atomicAdd(&g_deg[dst[e]], ew[e]);
        atomicAdd(&g_count[dst[e]], 1);
    }
}
// single block, 1024 threads: node norms + exclusive scan of g_count
__global__ void k_scan() {
    int tid = threadIdx.x;
    // node norms (deg complete after k_prep_edges)
#pragma unroll
    for (int j = 0; j < 16; j++) {
        int i = tid * 16 + j;
        float d = g_deg[i] + 1.0f;
        g_dinv[i] = rsqrtf(d);
        g_self[i] = 1.0f / d;
    }
    int c[16];
    int tot = 0;
#pragma unroll
    for (int j = 0; j < 16; j++) { c[j] = tot; tot += g_count[tid * 16 + j]; }
    __shared__ int s[1024];
    s[tid] = tot;
    __syncthreads();
    int mytot = tot;
    for (int off = 1; off < 1024; off <<= 1) {
        int v = (tid >= off) ? s[tid - off] : 0;
        __syncthreads();
        s[tid] += v;
        __syncthreads();
    }
    int incl = s[tid];
    int excl = incl - mytot;
#pragma unroll
    for (int j = 0; j < 16; j++) {
        int v = excl + c[j];
        g_rowptr[tid * 16 + j] = v;
        g_cursor[tid * 16 + j] = v;
    }
    if (tid == 1023) g_rowptr[NNODES] = incl;
}
__global__ void k_fill(const int* __restrict__ src, const int* __restrict__ dst,
                       const float* __restrict__ ew) {
    int e = blockIdx.x * blockDim.x + threadIdx.x;
    if (e < NEDGES) {
        int s = src[e], d = dst[e];
        float norm = g_dinv[s] * ew[e] * g_dinv[d];
        int p = atomicAdd(&g_cursor[d], 1);
        g_csrc[p] = s;
        g_cw[p] = norm;
    }
}

// ---------------- weight conversion: W [K,N] f32 -> Wt fp16 [Npad,K] ----------------
__global__ void k_wconv(const float* __restrict__ W, __half* __restrict__ Wt,
                        int K, int N) {
    __shared__ float t[32][33];
    int k0 = blockIdx.x * 32, nb0 = blockIdx.y * 32;
    int tx = threadIdx.x, ty = threadIdx.y;
    for (int r = ty; r < 32; r += 8) {
        int nn = nb0 + tx;
        t[r][tx] = (nn < N) ? W[(size_t)(k0 + r) * N + nn] : 0.f;
    }
    __syncthreads();
    for (int r = ty; r < 32; r += 8) {
        int nn = nb0 + r;
        Wt[(size_t)nn * K + k0 + tx] = __float2half(t[tx][r]);
    }
}

// ---------------- aggregation kernels (CSR gather, software-pipelined) ----------------
// MODE: 0 = f32 input (layer 1, x); 1 = fp16 input;
//       2 = post (fp16 input, add bias, relu) [layer 4]
template <int MODE>
__global__ void k_agg(const float* __restrict__ xf, const __half* __restrict__ inA,
                      const float* __restrict__ bias,
                      __half* __restrict__ outA, int F) {
    int n  = blockIdx.y;
    int f4 = blockIdx.x * blockDim.x + threadIdx.x;
    int F4 = F >> 2;
    if (f4 >= F4) return;

    auto loadrow = [&](int row, float4& v) {
        if (MODE == 0) {
            v = ((const float4*)(xf + (size_t)row * F))[f4];
        } else {
            const __half2* ph = ((const __half2*)(inA + (size_t)row * F)) + f4 * 2;
            float2 h0 = __half22float2(ph[0]);
            float2 h1 = __half22float2(ph[1]);
            v.x = h0.x; v.y = h0.y; v.z = h1.x; v.w = h1.y;
        }
    };

    float4 hv; loadrow(n, hv);
    float sc = g_self[n];
    float4 acc = make_float4(sc * hv.x, sc * hv.y, sc * hv.z, sc * hv.w);
    int beg = g_rowptr[n], end = g_rowptr[n + 1];
    if (beg < end) {
        int   s_cur = g_csrc[beg];
        float w_cur = g_cw[beg];
        for (int j = beg; j < end; j++) {
            int   s = s_cur;
            float w = w_cur;
            if (j + 1 < end) {            // prefetch next edge metadata
                s_cur = g_csrc[j + 1];
                w_cur = g_cw[j + 1];
            }
            float4 sv; loadrow(s, sv);
            acc.x += w * sv.x; acc.y += w * sv.y;
            acc.z += w * sv.z; acc.w += w * sv.w;
        }
    }
    if (MODE == 2) {
        float4 bb = ((const float4*)bias)[f4];
        acc.x = fmaxf(acc.x + bb.x, 0.f);
        acc.y = fmaxf(acc.y + bb.y, 0.f);
        acc.z = fmaxf(acc.z + bb.z, 0.f);
        acc.w = fmaxf(acc.w + bb.w, 0.f);
    }
    __half2* ph = ((__half2*)(outA + (size_t)n * F)) + f4 * 2;
    ph[0] = __floats2half2_rn(acc.x, acc.y);
    ph[1] = __floats2half2_rn(acc.z, acc.w);
}

// ---------------- mma.sync fp16 GEMM (single term) ----------------
// CTA 128x256, 512 threads (16 warps, warp tile 32x64), BK=64, 3-stage cp.async.
// A [M,K] fp16, B = Wt [Npad,K] fp16.  C = A @ B^T.
#define BM 128
#define BN 256
#define BKC 64
#define LDT 72                          // fp16 elems per row (144 B; bank-stride 4)
#define A_T (128 * LDT * 2)             // 18432 B
#define B_T (256 * LDT * 2)             // 36864 B
#define STAGE_B (A_T + B_T)             // 55296 B
#define NSTAGE 3
#define GEMM_SMEM (NSTAGE * STAGE_B)    // 165888 B

template <int MODE>
__global__ void __launch_bounds__(512, 1)
k_gemm_mma(const __half* __restrict__ Aa, const __half* __restrict__ Bw,
           __half* __restrict__ Oh, float* __restrict__ Cf,
           const float* __restrict__ bias,
           int K, int Ncols, int KC) {
    extern __shared__ char smem[];
    uint32_t sb = smem_u32(smem);
    int tid = threadIdx.x;
    int wid = tid >> 5, lane = tid & 31;
    int m0 = blockIdx.y * BM, n0 = blockIdx.x * BN;
    int wm = wid & 3;        // warp m tile (32 rows)
    int wn = wid >> 2;       // warp n tile (64 cols, 0..3)

    const __half* A0 = Aa + (size_t)m0 * K;
    const __half* B0 = Bw + (size_t)n0 * K;

    int ar = tid >> 2, ag = tid & 3;      // A: 128 rows, 4 threads/row, 2 groups each
    int br = tid >> 1, bg = (tid & 1) * 4; // B: 256 rows, 2 threads/row, 4 groups each
    auto load_chunk = [&](int c, int s) {
        uint32_t tb = sb + s * STAGE_B;
        size_t koff = (size_t)c * BKC;
#pragma unroll
        for (int t = 0; t < 2; t++) {
            int g = ag + t * 4;
            cp16(tb + (uint32_t)(ar * (LDT * 2) + g * 16),
                 A0 + (size_t)ar * K + koff + g * 8);
        }
#pragma unroll
        for (int t = 0; t < 4; t++) {
            int g = bg + t;
            cp16(tb + A_T + (uint32_t)(br * (LDT * 2) + g * 16),
                 B0 + (size_t)br * K + koff + g * 8);
        }
    };

    int quad = lane >> 3, r = lane & 7;
    uint32_t aOff = (uint32_t)(((wm * 32 + (quad & 1) * 8 + r) * LDT + (quad >> 1) * 8) * 2);
    uint32_t bOff = (uint32_t)(((wn * 64 + (quad >> 1) * 8 + r) * LDT + (quad & 1) * 8) * 2);

    float acc[2][8][4];
#pragma unroll
    for (int i = 0; i < 2; i++)
#pragma unroll
        for (int j = 0; j < 8; j++)
#pragma unroll
            for (int q = 0; q < 4; q++) acc[i][j][q] = 0.f;

    load_chunk(0, 0); cp_commit();
    if (KC > 1) { load_chunk(1, 1); cp_commit(); }

    for (int kc = 0; kc < KC; kc++) {
        int s = kc % NSTAGE;
        if (kc + 1 < KC) cp_wait<1>(); else cp_wait<0>();
        __syncthreads();

        uint32_t st = sb + s * STAGE_B;
#pragma unroll
        for (int ks = 0; ks < 4; ks++) {
            uint32_t ko = ks * 32;  // 16 elems * 2B
            uint32_t af[2][4], bf[4][4];
#pragma unroll
            for (int mi = 0; mi < 2; mi++)
                ldsm4(af[mi], st + aOff + mi * (16 * LDT * 2) + ko);
#pragma unroll
            for (int p = 0; p < 4; p++)
                ldsm4(bf[p], st + A_T + bOff + p * (16 * LDT * 2) + ko);
#pragma unroll
            for (int p = 0; p < 4; p++)
#pragma unroll
                for (int mi = 0; mi < 2; mi++)
#pragma unroll
                    for (int h = 0; h < 2; h++)
                        mma16816(acc[mi][2 * p + h], af[mi], &bf[p][h * 2]);
        }

        if (kc + 2 < KC) {
            load_chunk(kc + 2, (kc + 2) % NSTAGE);
            cp_commit();
        }
        __syncthreads();
    }

    // epilogue
    int cr = lane >> 2, cc = (lane & 3) * 2;
#pragma unroll
    for (int mi = 0; mi < 2; mi++) {
#pragma unroll
        for (int ni = 0; ni < 8; ni++) {
            int n = n0 + wn * 64 + ni * 8 + cc;
#pragma unroll
            for (int hh = 0; hh < 2; hh++) {
                int m = m0 + wm * 32 + mi * 16 + cr + hh * 8;
                float v0 = acc[mi][ni][hh * 2 + 0];
                float v1 = acc[mi][ni][hh * 2 + 1];
                if (MODE == 2) {
                    if (n < Ncols)     Cf[(size_t)m * Ncols + n]     = v0 + bias[n];
                    if (n + 1 < Ncols) Cf[(size_t)m * Ncols + n + 1] = v1 + bias[n + 1];
                } else {
                    if (MODE == 0) {
                        v0 = fmaxf(v0 + bias[n], 0.f);
                        v1 = fmaxf(v1 + bias[n + 1], 0.f);
                    }
                    *(__half2*)(Oh + (size_t)m * Ncols + n) = __floats2half2_rn(v0, v1);
                }
            }
        }
    }
}

// ---------------- host orchestration ----------------
static inline void launch_gemm(int mode,
                               const __half* Aa, const __half* Bw,
                               __half* Oh, float* Cf, const float* bias,
                               int K, int Ncols, int Npad) {
    dim3 grid(Npad / BN, NNODES / BM);
    if (mode == 0) {
        cudaFuncSetAttribute(k_gemm_mma<0>, cudaFuncAttributeMaxDynamicSharedMemorySize, GEMM_SMEM);
        k_gemm_mma<0><<<grid, 512, GEMM_SMEM>>>(Aa, Bw, Oh, Cf, bias, K, Ncols, K / BKC);
    } else if (mode == 1) {
        cudaFuncSetAttribute(k_gemm_mma<1>, cudaFuncAttributeMaxDynamicSharedMemorySize, GEMM_SMEM);
        k_gemm_mma<1><<<grid, 512, GEMM_SMEM>>>(Aa, Bw, Oh, Cf, bias, K, Ncols, K / BKC);
    } else {
        cudaFuncSetAttribute(k_gemm_mma<2>, cudaFuncAttributeMaxDynamicSharedMemorySize, GEMM_SMEM);
        k_gemm_mma<2><<<grid, 512, GEMM_SMEM>>>(Aa, Bw, Oh, Cf, bias, K, Ncols, K / BKC);
    }
}

static inline void launch_wconv(const float* W, __half* Wt, int K, int N, int Npad) {
    dim3 grid(K / 32, Npad / 32);
    k_wconv<<<grid, dim3(32, 8)>>>(W, Wt, K, N);
}

extern "C" void kernel_launch(void* const* d_in, const int* in_sizes, int n_in,
                              void* d_out, int out_size) {
    const float* x    = (const float*)d_in[0];
    const int*   esrc = (const int*)d_in[1];
    const int*   edst = (const int*)d_in[2];
    const float* ew   = (const float*)d_in[3];
    const float* W1 = (const float*)d_in[4];
    const float* b1 = (const float*)d_in[5];
    const float* W2 = (const float*)d_in[6];
    const float* b2 = (const float*)d_in[7];
    const float* W3 = (const float*)d_in[8];
    const float* b3 = (const float*)d_in[9];
    const float* W4 = (const float*)d_in[10];
    const float* b4 = (const float*)d_in[11];
    const float* Wout = (const float*)d_in[12];
    const float* bout = (const float*)d_in[13];
    float* out = (float*)d_out;

    __half *abuf, *gbuf, *wt;
    cudaGetSymbolAddress((void**)&abuf, g_a);
    cudaGetSymbolAddress((void**)&gbuf, g_g);
    cudaGetSymbolAddress((void**)&wt, g_wt);

    // graph prep
    k_prep_zero<<<NNODES / 256, 256>>>();
    k_prep_edges<<<NEDGES / 256, 256>>>(esrc, edst, ew);
    k_scan<<<1, 1024>>>();
    k_fill<<<NEDGES / 256, 256>>>(esrc, edst, ew);

    auto agg_grid = [](int F) { return dim3(((F >> 2) + 255) / 256, NNODES); };

    // L1: g = agg(x) [512]; a = relu(g W1 + b1) [1024]
    k_agg<0><<<agg_grid(512), 256>>>(x, nullptr, nullptr, gbuf, 512);
    launch_wconv(W1, wt, 512, 1024, 1024);
    launch_gemm(0, gbuf, wt, abuf, nullptr, b1, 512, 1024, 1024);

    // L2: g = agg(a) [1024]; a = relu(g W2 + b2) [2048]
    k_agg<1><<<agg_grid(1024), 256>>>(nullptr, abuf, nullptr, gbuf, 1024);
    launch_wconv(W2, wt, 1024, 2048, 2048);
    launch_gemm(0, gbuf, wt, abuf, nullptr, b2, 1024, 2048, 2048);

    // L3: g = agg(a) [2048]; a = relu(g W3 + b3) [4096]
    k_agg<1><<<agg_grid(2048), 256>>>(nullptr, abuf, nullptr, gbuf, 2048);
    launch_wconv(W3, wt, 2048, 4096, 4096);
    launch_gemm(0, gbuf, wt, abuf, nullptr, b3, 2048, 4096, 4096);

    // L4 (agg after): h = a W4 [2048]; a = relu(agg(h) + b4)
    launch_wconv(W4, wt, 4096, 2048, 2048);
    launch_gemm(1, abuf, wt, gbuf, nullptr, nullptr, 4096, 2048, 2048);
    k_agg<2><<<agg_grid(2048), 256>>>(nullptr, gbuf, b4, abuf, 2048);

    // L5 (output): out = a Wout + bout [1000]
    launch_wconv(Wout, wt, 2048, 1000, 1024);
    launch_gemm(2, abuf, wt, nullptr, out, bout, 2048, 1000, 1024);
}

// round 13
// speedup vs baseline: 1.0826x; 1.0826x over previous
#include <cuda_runtime.h>
#include <cuda_fp16.h>
#include <cstdint>

#define NNODES 16384
#define NEDGES 65536
#define MAXF   4096

// ---------------- scratch (device globals; no allocation) ----------------
__device__ __half g_a[(size_t)NNODES * MAXF];     // activation buffer A (fp16)
__device__ __half g_g[(size_t)NNODES * MAXF];     // buffer B (fp16)
__device__ __half g_wt[(size_t)4096 * 4096];      // transposed weights fp16 [Npad,K]
__device__ float g_deg[NNODES];
__device__ float g_dinv[NNODES];
__device__ float g_self[NNODES];
__device__ int   g_count[NNODES];
__device__ int   g_rowptr[NNODES + 1];
__device__ int   g_cursor[NNODES];
__device__ int   g_csrc[NEDGES];
__device__ float g_cw[NEDGES];

// ---------------- PTX helpers (baseline PTX only) ----------------
__device__ __forceinline__ uint32_t smem_u32(const void* p) {
    uint32_t a;
    asm("{ .reg .u64 t; cvta.to.shared.u64 t, %1; cvt.u32.u64 %0, t; }" : "=r"(a) : "l"(p));
    return a;
}
__device__ __forceinline__ void cp16(uint32_t s, const void* g) {
    asm volatile("cp.async.cg.shared.global [%0], [%1], 16;" :: "r"(s), "l"(g));
}
__device__ __forceinline__ void cp_commit() { asm volatile("cp.async.commit_group;" ::: "memory"); }
template <int N>
__device__ __forceinline__ void cp_wait() { asm volatile("cp.async.wait_group %0;" :: "n"(N) : "memory"); }

__device__ __forceinline__ void ldsm4(uint32_t* r, uint32_t addr) {
    asm volatile("ldmatrix.sync.aligned.m8n8.x4.shared.b16 {%0,%1,%2,%3}, [%4];"
                 : "=r"(r[0]), "=r"(r[1]), "=r"(r[2]), "=r"(r[3]) : "r"(addr));
}
__device__ __forceinline__ void mma16816(float* d, const uint32_t* a, const uint32_t* b) {
    asm volatile(
        "mma.sync.aligned.m16n8k16.row.col.f32.f16.f16.f32 "
        "{%0,%1,%2,%3}, {%4,%5,%6,%7}, {%8,%9}, {%0,%1,%2,%3};"
        : "+f"(d[0]), "+f"(d[1]), "+f"(d[2]), "+f"(d[3])
        : "r"(a[0]), "r"(a[1]), "r"(a[2]), "r"(a[3]), "r"(b[0]), "r"(b[1]));
}

// ---------------- graph prep ----------------
__global__ void k_prep_zero() {
    int i = blockIdx.x * blockDim.x + threadIdx.x;
    if (i < NNODES) { g_deg[i] = 0.f; g_count[i] = 0; }
}
__global__ void k_prep_edges(const int* __restrict__ src, const int* __restrict__ dst,
                             const float* __restrict__ ew) {
    int e = blockIdx.x * blockDim.x + threadIdx.x;
    if (e < NEDGES) {
        atomicAdd(&g_deg[dst[e]], ew[e]);
        atomicAdd(&g_count[dst[e]], 1);
    }
}
// single block, 1024 threads: node norms + exclusive scan of g_count
__global__ void k_scan() {
    int tid = threadIdx.x;
#pragma unroll
    for (int j = 0; j < 16; j++) {
        int i = tid * 16 + j;
        float d = g_deg[i] + 1.0f;
        g_dinv[i] = rsqrtf(d);
        g_self[i] = 1.0f / d;
    }
    int c[16];
    int tot = 0;
#pragma unroll
    for (int j = 0; j < 16; j++) { c[j] = tot; tot += g_count[tid * 16 + j]; }
    __shared__ int s[1024];
    s[tid] = tot;
    __syncthreads();
    int mytot = tot;
    for (int off = 1; off < 1024; off <<= 1) {
        int v = (tid >= off) ? s[tid - off] : 0;
        __syncthreads();
        s[tid] += v;
        __syncthreads();
    }
    int incl = s[tid];
    int excl = incl - mytot;
#pragma unroll
    for (int j = 0; j < 16; j++) {
        int v = excl + c[j];
        g_rowptr[tid * 16 + j] = v;
        g_cursor[tid * 16 + j] = v;
    }
    if (tid == 1023) g_rowptr[NNODES] = incl;
}
__global__ void k_fill(const int* __restrict__ src, const int* __restrict__ dst,
                       const float* __restrict__ ew) {
    int e = blockIdx.x * blockDim.x + threadIdx.x;
    if (e < NEDGES) {
        int s = src[e], d = dst[e];
        float norm = g_dinv[s] * ew[e] * g_dinv[d];
        int p = atomicAdd(&g_cursor[d], 1);
        g_csrc[p] = s;
        g_cw[p] = norm;
    }
}

// ---------------- weight conversion: W [K,N] f32 -> Wt fp16 [Npad,K] ----------------
__global__ void k_wconv(const float* __restrict__ W, __half* __restrict__ Wt,
                        int K, int N) {
    __shared__ float t[32][33];
    int k0 = blockIdx.x * 32, nb0 = blockIdx.y * 32;
    int tx = threadIdx.x, ty = threadIdx.y;
    for (int r = ty; r < 32; r += 8) {
        int nn = nb0 + tx;
        t[r][tx] = (nn < N) ? W[(size_t)(k0 + r) * N + nn] : 0.f;
    }
    __syncthreads();
    for (int r = ty; r < 32; r += 8) {
        int nn = nb0 + r;
        Wt[(size_t)nn * K + k0 + tx] = __float2half(t[tx][r]);
    }
}

// ---------------- aggregation kernels (CSR gather, software-pipelined) ----------------
// MODE: 0 = f32 input (layer 1, x); 1 = fp16 input;
//       2 = post (fp16 input, add bias, relu) [layer 4]
template <int MODE>
__global__ void k_agg(const float* __restrict__ xf, const __half* __restrict__ inA,
                      const float* __restrict__ bias,
                      __half* __restrict__ outA, int F) {
    int n  = blockIdx.y;
    int f4 = blockIdx.x * blockDim.x + threadIdx.x;
    int F4 = F >> 2;
    if (f4 >= F4) return;

    auto loadrow = [&](int row, float4& v) {
        if (MODE == 0) {
            v = ((const float4*)(xf + (size_t)row * F))[f4];
        } else {
            const __half2* ph = ((const __half2*)(inA + (size_t)row * F)) + f4 * 2;
            float2 h0 = __half22float2(ph[0]);
            float2 h1 = __half22float2(ph[1]);
            v.x = h0.x; v.y = h0.y; v.z = h1.x; v.w = h1.y;
        }
    };

    float4 hv; loadrow(n, hv);
    float sc = g_self[n];
    float4 acc = make_float4(sc * hv.x, sc * hv.y, sc * hv.z, sc * hv.w);
    int beg = g_rowptr[n], end = g_rowptr[n + 1];
    if (beg < end) {
        int   s_cur = g_csrc[beg];
        float w_cur = g_cw[beg];
        for (int j = beg; j < end; j++) {
            int   s = s_cur;
            float w = w_cur;
            if (j + 1 < end) {            // prefetch next edge metadata
                s_cur = g_csrc[j + 1];
                w_cur = g_cw[j + 1];
            }
            float4 sv; loadrow(s, sv);
            acc.x += w * sv.x; acc.y += w * sv.y;
            acc.z += w * sv.z; acc.w += w * sv.w;
        }
    }
    if (MODE == 2) {
        float4 bb = ((const float4*)bias)[f4];
        acc.x = fmaxf(acc.x + bb.x, 0.f);
        acc.y = fmaxf(acc.y + bb.y, 0.f);
        acc.z = fmaxf(acc.z + bb.z, 0.f);
        acc.w = fmaxf(acc.w + bb.w, 0.f);
    }
    __half2* ph = ((__half2*)(outA + (size_t)n * F)) + f4 * 2;
    ph[0] = __floats2half2_rn(acc.x, acc.y);
    ph[1] = __floats2half2_rn(acc.z, acc.w);
}

// ---------------- mma.sync fp16 GEMM (single term) ----------------
// CTA 128x256, 512 threads (16 warps, warp tile 32x64), BK=32, 4-stage cp.async.
// A [M,K] fp16, B = Wt [Npad,K] fp16.  C = A @ B^T.
#define BM 128
#define BN 256
#define BKC 32
#define LDT 40                          // fp16 elems per row (80 B)
#define A_T (128 * LDT * 2)             // 10240 B
#define B_T (256 * LDT * 2)             // 20480 B
#define STAGE_B (A_T + B_T)             // 30720 B
#define NSTAGE 4
#define GEMM_SMEM (NSTAGE * STAGE_B)    // 122880 B

template <int MODE>
__global__ void __launch_bounds__(512, 1)
k_gemm_mma(const __half* __restrict__ Aa, const __half* __restrict__ Bw,
           __half* __restrict__ Oh, float* __restrict__ Cf,
           const float* __restrict__ bias,
           int K, int Ncols, int KC) {
    extern __shared__ char smem[];
    uint32_t sb = smem_u32(smem);
    int tid = threadIdx.x;
    int wid = tid >> 5, lane = tid & 31;
    int m0 = blockIdx.y * BM, n0 = blockIdx.x * BN;
    int wm = wid & 3;        // warp m tile (32 rows)
    int wn = wid >> 2;       // warp n tile (64 cols, 0..3)

    const __half* A0 = Aa + (size_t)m0 * K;
    const __half* B0 = Bw + (size_t)n0 * K;

    int lrow = tid >> 2;       // 0..127
    int lg   = tid & 3;        // 16B group
    auto load_chunk = [&](int c, int s) {
        uint32_t tb = sb + s * STAGE_B;
        size_t koff = (size_t)c * BKC;
        uint32_t so = (uint32_t)(lrow * (LDT * 2) + lg * 16);
        size_t go = (size_t)lrow * K + koff + lg * 8;
        cp16(tb + so, A0 + go);
#pragma unroll
        for (int half = 0; half < 2; half++) {
            int row = lrow + half * 128;
            uint32_t sob = (uint32_t)(row * (LDT * 2) + lg * 16);
            size_t gob = (size_t)row * K + koff + lg * 8;
            cp16(tb + A_T + sob, B0 + gob);
        }
    };

    int quad = lane >> 3, r = lane & 7;
    uint32_t aOff = (uint32_t)(((wm * 32 + (quad & 1) * 8 + r) * LDT + (quad >> 1) * 8) * 2);
    uint32_t bOff = (uint32_t)(((wn * 64 + (quad >> 1) * 8 + r) * LDT + (quad & 1) * 8) * 2);

    float acc[2][8][4];
#pragma unroll
    for (int i = 0; i < 2; i++)
#pragma unroll
        for (int j = 0; j < 8; j++)
#pragma unroll
            for (int q = 0; q < 4; q++) acc[i][j][q] = 0.f;

    // prologue: fill 3 of 4 stages
    load_chunk(0, 0); cp_commit();
    if (KC > 1) { load_chunk(1, 1); cp_commit(); }
    if (KC > 2) { load_chunk(2, 2); cp_commit(); }

    for (int kc = 0; kc < KC; kc++) {
        int s = kc & 3;
        int after = (kc + 3 < KC ? 3 : KC - 1 - kc);
        if (after >= 2) cp_wait<2>();
        else if (after == 1) cp_wait<1>();
        else cp_wait<0>();
        __syncthreads();

        uint32_t st = sb + s * STAGE_B;
#pragma unroll
        for (int ks = 0; ks < 2; ks++) {
            uint32_t ko = ks * 32;  // 16 elems * 2B
            uint32_t af[2][4], bf[4][4];
#pragma unroll
            for (int mi = 0; mi < 2; mi++)
                ldsm4(af[mi], st + aOff + mi * (16 * LDT * 2) + ko);
#pragma unroll
            for (int p = 0; p < 4; p++)
                ldsm4(bf[p], st + A_T + bOff + p * (16 * LDT * 2) + ko);
#pragma unroll
            for (int p = 0; p < 4; p++)
#pragma unroll
                for (int mi = 0; mi < 2; mi++)
#pragma unroll
                    for (int h = 0; h < 2; h++)
                        mma16816(acc[mi][2 * p + h], af[mi], &bf[p][h * 2]);
        }

        if (kc + 3 < KC) {
            load_chunk(kc + 3, (kc + 3) & 3);
            cp_commit();
        }
        __syncthreads();
    }

    // epilogue
    int cr = lane >> 2, cc = (lane & 3) * 2;
#pragma unroll
    for (int mi = 0; mi < 2; mi++) {
#pragma unroll
        for (int ni = 0; ni < 8; ni++) {
            int n = n0 + wn * 64 + ni * 8 + cc;
#pragma unroll
            for (int hh = 0; hh < 2; hh++) {
                int m = m0 + wm * 32 + mi * 16 + cr + hh * 8;
                float v0 = acc[mi][ni][hh * 2 + 0];
                float v1 = acc[mi][ni][hh * 2 + 1];
                if (MODE == 2) {
                    if (n < Ncols)     Cf[(size_t)m * Ncols + n]     = v0 + bias[n];
                    if (n + 1 < Ncols) Cf[(size_t)m * Ncols + n + 1] = v1 + bias[n + 1];
                } else {
                    if (MODE == 0) {
                        v0 = fmaxf(v0 + bias[n], 0.f);
                        v1 = fmaxf(v1 + bias[n + 1], 0.f);
                    }
                    *(__half2*)(Oh + (size_t)m * Ncols + n) = __floats2half2_rn(v0, v1);
                }
            }
        }
    }
}

// ---------------- host orchestration ----------------
static inline void launch_gemm(int mode,
                               const __half* Aa, const __half* Bw,
                               __half* Oh, float* Cf, const float* bias,
                               int K, int Ncols, int Npad) {
    dim3 grid(Npad / BN, NNODES / BM);
    if (mode == 0) {
        cudaFuncSetAttribute(k_gemm_mma<0>, cudaFuncAttributeMaxDynamicSharedMemorySize, GEMM_SMEM);
        k_gemm_mma<0><<<grid, 512, GEMM_SMEM>>>(Aa, Bw, Oh, Cf, bias, K, Ncols, K / BKC);
    } else if (mode == 1) {
        cudaFuncSetAttribute(k_gemm_mma<1>, cudaFuncAttributeMaxDynamicSharedMemorySize, GEMM_SMEM);
        k_gemm_mma<1><<<grid, 512, GEMM_SMEM>>>(Aa, Bw, Oh, Cf, bias, K, Ncols, K / BKC);
    } else {
        cudaFuncSetAttribute(k_gemm_mma<2>, cudaFuncAttributeMaxDynamicSharedMemorySize, GEMM_SMEM);
        k_gemm_mma<2><<<grid, 512, GEMM_SMEM>>>(Aa, Bw, Oh, Cf, bias, K, Ncols, K / BKC);
    }
}

static inline void launch_wconv(const float* W, __half* Wt, int K, int N, int Npad) {
    dim3 grid(K / 32, Npad / 32);
    k_wconv<<<grid, dim3(32, 8)>>>(W, Wt, K, N);
}

extern "C" void kernel_launch(void* const* d_in, const int* in_sizes, int n_in,
                              void* d_out, int out_size) {
    const float* x    = (const float*)d_in[0];
    const int*   esrc = (const int*)d_in[1];
    const int*   edst = (const int*)d_in[2];
    const float* ew   = (const float*)d_in[3];
    const float* W1 = (const float*)d_in[4];
    const float* b1 = (const float*)d_in[5];
    const float* W2 = (const float*)d_in[6];
    const float* b2 = (const float*)d_in[7];
    const float* W3 = (const float*)d_in[8];
    const float* b3 = (const float*)d_in[9];
    const float* W4 = (const float*)d_in[10];
    const float* b4 = (const float*)d_in[11];
    const float* Wout = (const float*)d_in[12];
    const float* bout = (const float*)d_in[13];
    float* out = (float*)d_out;

    __half *abuf, *gbuf, *wt;
    cudaGetSymbolAddress((void**)&abuf, g_a);
    cudaGetSymbolAddress((void**)&gbuf, g_g);
    cudaGetSymbolAddress((void**)&wt, g_wt);

    // graph prep
    k_prep_zero<<<NNODES / 256, 256>>>();
    k_prep_edges<<<NEDGES / 256, 256>>>(esrc, edst, ew);
    k_scan<<<1, 1024>>>();
    k_fill<<<NEDGES / 256, 256>>>(esrc, edst, ew);

    auto agg_grid = [](int F) { return dim3(((F >> 2) + 255) / 256, NNODES); };

    // L1: g = agg(x) [512]; a = relu(g W1 + b1) [1024]
    k_agg<0><<<agg_grid(512), 256>>>(x, nullptr, nullptr, gbuf, 512);
    launch_wconv(W1, wt, 512, 1024, 1024);
    launch_gemm(0, gbuf, wt, abuf, nullptr, b1, 512, 1024, 1024);

    // L2: g = agg(a) [1024]; a = relu(g W2 + b2) [2048]
    k_agg<1><<<agg_grid(1024), 256>>>(nullptr, abuf, nullptr, gbuf, 1024);
    launch_wconv(W2, wt, 1024, 2048, 2048);
    launch_gemm(0, gbuf, wt, abuf, nullptr, b2, 1024, 2048, 2048);

    // L3: g = agg(a) [2048]; a = relu(g W3 + b3) [4096]
    k_agg<1><<<agg_grid(2048), 256>>>(nullptr, abuf, nullptr, gbuf, 2048);
    launch_wconv(W3, wt, 2048, 4096, 4096);
    launch_gemm(0, gbuf, wt, abuf, nullptr, b3, 2048, 4096, 4096);

    // L4 (agg after): h = a W4 [2048]; a = relu(agg(h) + b4)
    launch_wconv(W4, wt, 4096, 2048, 2048);
    launch_gemm(1, abuf, wt, gbuf, nullptr, nullptr, 4096, 2048, 2048);
    k_agg<2><<<agg_grid(2048), 256>>>(nullptr, gbuf, b4, abuf, 2048);

    // L5 (output): out = a Wout + bout [1000]
    launch_wconv(Wout, wt, 2048, 1000, 1024);
    launch_gemm(2, abuf, wt, nullptr, out, bout, 2048, 1000, 1024);
}

// round 14
// speedup vs baseline: 1.1304x; 1.0441x over previous
#include <cuda_runtime.h>
#include <cuda_fp16.h>
#include <cstdint>

#define NNODES 16384
#define NEDGES 65536
#define MAXF   4096

// ---------------- scratch (device globals; no allocation) ----------------
__device__ __half g_a[(size_t)NNODES * MAXF];     // activation buffer A (fp16)
__device__ __half g_g[(size_t)NNODES * MAXF];     // buffer B (fp16)
__device__ __half g_wt[(size_t)4096 * 4096];      // transposed weights fp16 [Npad,K]
__device__ float g_deg[NNODES];
__device__ float g_dinv[NNODES];
__device__ float g_self[NNODES];
__device__ int   g_count[NNODES];
__device__ int   g_rowptr[NNODES + 1];
__device__ int   g_cursor[NNODES];
__device__ int   g_csrc[NEDGES];
__device__ float g_cw[NEDGES];

// ---------------- PTX helpers (baseline PTX only) ----------------
__device__ __forceinline__ uint32_t smem_u32(const void* p) {
    uint32_t a;
    asm("{ .reg .u64 t; cvta.to.shared.u64 t, %1; cvt.u32.u64 %0, t; }" : "=r"(a) : "l"(p));
    return a;
}
__device__ __forceinline__ void cp16(uint32_t s, const void* g) {
    asm volatile("cp.async.cg.shared.global [%0], [%1], 16;" :: "r"(s), "l"(g));
}
__device__ __forceinline__ void cp_commit() { asm volatile("cp.async.commit_group;" ::: "memory"); }
template <int N>
__device__ __forceinline__ void cp_wait() { asm volatile("cp.async.wait_group %0;" :: "n"(N) : "memory"); }

__device__ __forceinline__ void ldsm4(uint32_t* r, uint32_t addr) {
    asm volatile("ldmatrix.sync.aligned.m8n8.x4.shared.b16 {%0,%1,%2,%3}, [%4];"
                 : "=r"(r[0]), "=r"(r[1]), "=r"(r[2]), "=r"(r[3]) : "r"(addr));
}
__device__ __forceinline__ void mma16816(float* d, const uint32_t* a, const uint32_t* b) {
    asm volatile(
        "mma.sync.aligned.m16n8k16.row.col.f32.f16.f16.f32 "
        "{%0,%1,%2,%3}, {%4,%5,%6,%7}, {%8,%9}, {%0,%1,%2,%3};"
        : "+f"(d[0]), "+f"(d[1]), "+f"(d[2]), "+f"(d[3])
        : "r"(a[0]), "r"(a[1]), "r"(a[2]), "r"(a[3]), "r"(b[0]), "r"(b[1]));
}

// ---------------- graph prep ----------------
__global__ void k_prep_zero() {
    int i = blockIdx.x * blockDim.x + threadIdx.x;
    if (i < NNODES) { g_deg[i] = 0.f; g_count[i] = 0; }
}
__global__ void k_prep_edges(const int* __restrict__ src, const int* __restrict__ dst,
                             const float* __restrict__ ew) {
    int e = blockIdx.x * blockDim.x + threadIdx.x;
    if (e < NEDGES) {
        atomicAdd(&g_deg[dst[e]], ew[e]);
        atomicAdd(&g_count[dst[e]], 1);
    }
}
// single block, 1024 threads: node norms + exclusive scan of g_count
__global__ void k_scan() {
    int tid = threadIdx.x;
#pragma unroll
    for (int j = 0; j < 16; j++) {
        int i = tid * 16 + j;
        float d = g_deg[i] + 1.0f;
        g_dinv[i] = rsqrtf(d);
        g_self[i] = 1.0f / d;
    }
    int c[16];
    int tot = 0;
#pragma unroll
    for (int j = 0; j < 16; j++) { c[j] = tot; tot += g_count[tid * 16 + j]; }
    __shared__ int s[1024];
    s[tid] = tot;
    __syncthreads();
    int mytot = tot;
    for (int off = 1; off < 1024; off <<= 1) {
        int v = (tid >= off) ? s[tid - off] : 0;
        __syncthreads();
        s[tid] += v;
        __syncthreads();
    }
    int incl = s[tid];
    int excl = incl - mytot;
#pragma unroll
    for (int j = 0; j < 16; j++) {
        int v = excl + c[j];
        g_rowptr[tid * 16 + j] = v;
        g_cursor[tid * 16 + j] = v;
    }
    if (tid == 1023) g_rowptr[NNODES] = incl;
}
__global__ void k_fill(const int* __restrict__ src, const int* __restrict__ dst,
                       const float* __restrict__ ew) {
    int e = blockIdx.x * blockDim.x + threadIdx.x;
    if (e < NEDGES) {
        int s = src[e], d = dst[e];
        float norm = g_dinv[s] * ew[e] * g_dinv[d];
        int p = atomicAdd(&g_cursor[d], 1);
        g_csrc[p] = s;
        g_cw[p] = norm;
    }
}

// ---------------- weight conversion: W [K,N] f32 -> Wt fp16 [Npad,K] ----------------
__global__ void k_wconv(const float* __restrict__ W, __half* __restrict__ Wt,
                        int K, int N) {
    __shared__ float t[32][33];
    int k0 = blockIdx.x * 32, nb0 = blockIdx.y * 32;
    int tx = threadIdx.x, ty = threadIdx.y;
    for (int r = ty; r < 32; r += 8) {
        int nn = nb0 + tx;
        t[r][tx] = (nn < N) ? W[(size_t)(k0 + r) * N + nn] : 0.f;
    }
    __syncthreads();
    for (int r = ty; r < 32; r += 8) {
        int nn = nb0 + r;
        Wt[(size_t)nn * K + k0 + tx] = __float2half(t[tx][r]);
    }
}

// ---------------- aggregation kernels (CSR gather, 16B vectorized) ----------------
// MODE 0: f32 input (layer 1, x), 4 floats/thread, no bias/relu
// MODE 1: fp16 input, 8 halves/thread, no bias/relu
// MODE 2: fp16 input, 8 halves/thread, +bias, relu (post-GEMM, layer 4)
template <int MODE>
__global__ void k_agg(const float* __restrict__ xf, const __half* __restrict__ inA,
                      const float* __restrict__ bias,
                      __half* __restrict__ outA, int F) {
    int n = blockIdx.y;
    int v = blockIdx.x * blockDim.x + threadIdx.x;

    if (MODE == 0) {
        int F4 = F >> 2;
        if (v >= F4) return;
        const float4* base = (const float4*)xf;
        float sc = g_self[n];
        float4 hv = base[(size_t)n * F4 + v];
        float4 acc = make_float4(sc * hv.x, sc * hv.y, sc * hv.z, sc * hv.w);
        int beg = g_rowptr[n], end = g_rowptr[n + 1];
        for (int j = beg; j < end; j++) {
            int   s = g_csrc[j];
            float w = g_cw[j];
            float4 sv = base[(size_t)s * F4 + v];
            acc.x += w * sv.x; acc.y += w * sv.y;
            acc.z += w * sv.z; acc.w += w * sv.w;
        }
        union { uint2 u; __half2 h[2]; } o;
        o.h[0] = __floats2half2_rn(acc.x, acc.y);
        o.h[1] = __floats2half2_rn(acc.z, acc.w);
        ((uint2*)(outA + (size_t)n * F))[v] = o.u;
    } else {
        int F8 = F >> 3;
        if (v >= F8) return;
        const uint4* base = (const uint4*)inA;
        float sc = g_self[n];
        union { uint4 u; __half2 h[4]; } r;
        r.u = base[(size_t)n * F8 + v];
        float a[8];
#pragma unroll
        for (int q = 0; q < 4; q++) {
            float2 f = __half22float2(r.h[q]);
            a[2 * q + 0] = sc * f.x;
            a[2 * q + 1] = sc * f.y;
        }
        int beg = g_rowptr[n], end = g_rowptr[n + 1];
        for (int j = beg; j < end; j++) {
            int   s = g_csrc[j];
            float w = g_cw[j];
            union { uint4 u; __half2 h[4]; } rv;
            rv.u = base[(size_t)s * F8 + v];
#pragma unroll
            for (int q = 0; q < 4; q++) {
                float2 f = __half22float2(rv.h[q]);
                a[2 * q + 0] += w * f.x;
                a[2 * q + 1] += w * f.y;
            }
        }
        if (MODE == 2) {
            float4 b0 = ((const float4*)bias)[2 * v + 0];
            float4 b1 = ((const float4*)bias)[2 * v + 1];
            a[0] = fmaxf(a[0] + b0.x, 0.f); a[1] = fmaxf(a[1] + b0.y, 0.f);
            a[2] = fmaxf(a[2] + b0.z, 0.f); a[3] = fmaxf(a[3] + b0.w, 0.f);
            a[4] = fmaxf(a[4] + b1.x, 0.f); a[5] = fmaxf(a[5] + b1.y, 0.f);
            a[6] = fmaxf(a[6] + b1.z, 0.f); a[7] = fmaxf(a[7] + b1.w, 0.f);
        }
        union { uint4 u; __half2 h[4]; } o;
#pragma unroll
        for (int q = 0; q < 4; q++)
            o.h[q] = __floats2half2_rn(a[2 * q + 0], a[2 * q + 1]);
        ((uint4*)(outA + (size_t)n * F))[v] = o.u;
    }
}

// ---------------- mma.sync fp16 GEMM (single term) ----------------
// CTA 128x256, 512 threads (16 warps, warp tile 32x64), BK=32, 4-stage cp.async.
// A [M,K] fp16, B = Wt [Npad,K] fp16.  C = A @ B^T.
#define BM 128
#define BN 256
#define BKC 32
#define LDT 40                          // fp16 elems per row (80 B)
#define A_T (128 * LDT * 2)             // 10240 B
#define B_T (256 * LDT * 2)             // 20480 B
#define STAGE_B (A_T + B_T)             // 30720 B
#define NSTAGE 4
#define GEMM_SMEM (NSTAGE * STAGE_B)    // 122880 B

template <int MODE>
__global__ void __launch_bounds__(512, 1)
k_gemm_mma(const __half* __restrict__ Aa, const __half* __restrict__ Bw,
           __half* __restrict__ Oh, float* __restrict__ Cf,
           const float* __restrict__ bias,
           int K, int Ncols, int KC) {
    extern __shared__ char smem[];
    uint32_t sb = smem_u32(smem);
    int tid = threadIdx.x;
    int wid = tid >> 5, lane = tid & 31;
    int m0 = blockIdx.y * BM, n0 = blockIdx.x * BN;
    int wm = wid & 3;        // warp m tile (32 rows)
    int wn = wid >> 2;       // warp n tile (64 cols, 0..3)

    const __half* A0 = Aa + (size_t)m0 * K;
    const __half* B0 = Bw + (size_t)n0 * K;

    int lrow = tid >> 2;       // 0..127
    int lg   = tid & 3;        // 16B group
    auto load_chunk = [&](int c, int s) {
        uint32_t tb = sb + s * STAGE_B;
        size_t koff = (size_t)c * BKC;
        uint32_t so = (uint32_t)(lrow * (LDT * 2) + lg * 16);
        size_t go = (size_t)lrow * K + koff + lg * 8;
        cp16(tb + so, A0 + go);
#pragma unroll
        for (int half = 0; half < 2; half++) {
            int row = lrow + half * 128;
            uint32_t sob = (uint32_t)(row * (LDT * 2) + lg * 16);
            size_t gob = (size_t)row * K + koff + lg * 8;
            cp16(tb + A_T + sob, B0 + gob);
        }
    };

    int quad = lane >> 3, r = lane & 7;
    uint32_t aOff = (uint32_t)(((wm * 32 + (quad & 1) * 8 + r) * LDT + (quad >> 1) * 8) * 2);
    uint32_t bOff = (uint32_t)(((wn * 64 + (quad >> 1) * 8 + r) * LDT + (quad & 1) * 8) * 2);

    float acc[2][8][4];
#pragma unroll
    for (int i = 0; i < 2; i++)
#pragma unroll
        for (int j = 0; j < 8; j++)
#pragma unroll
            for (int q = 0; q < 4; q++) acc[i][j][q] = 0.f;

    // prologue: fill 3 of 4 stages
    load_chunk(0, 0); cp_commit();
    if (KC > 1) { load_chunk(1, 1); cp_commit(); }
    if (KC > 2) { load_chunk(2, 2); cp_commit(); }

    for (int kc = 0; kc < KC; kc++) {
        int s = kc & 3;
        int after = (kc + 3 < KC ? 3 : KC - 1 - kc);
        if (after >= 2) cp_wait<2>();
        else if (after == 1) cp_wait<1>();
        else cp_wait<0>();
        __syncthreads();

        uint32_t st = sb + s * STAGE_B;
#pragma unroll
        for (int ks = 0; ks < 2; ks++) {
            uint32_t ko = ks * 32;  // 16 elems * 2B
            uint32_t af[2][4], bf[4][4];
#pragma unroll
            for (int mi = 0; mi < 2; mi++)
                ldsm4(af[mi], st + aOff + mi * (16 * LDT * 2) + ko);
#pragma unroll
            for (int p = 0; p < 4; p++)
                ldsm4(bf[p], st + A_T + bOff + p * (16 * LDT * 2) + ko);
#pragma unroll
            for (int p = 0; p < 4; p++)
#pragma unroll
                for (int mi = 0; mi < 2; mi++)
#pragma unroll
                    for (int h = 0; h < 2; h++)
                        mma16816(acc[mi][2 * p + h], af[mi], &bf[p][h * 2]);
        }

        if (kc + 3 < KC) {
            load_chunk(kc + 3, (kc + 3) & 3);
            cp_commit();
        }
        __syncthreads();
    }

    // epilogue
    int cr = lane >> 2, cc = (lane & 3) * 2;
#pragma unroll
    for (int mi = 0; mi < 2; mi++) {
#pragma unroll
        for (int ni = 0; ni < 8; ni++) {
            int n = n0 + wn * 64 + ni * 8 + cc;
#pragma unroll
            for (int hh = 0; hh < 2; hh++) {
                int m = m0 + wm * 32 + mi * 16 + cr + hh * 8;
                float v0 = acc[mi][ni][hh * 2 + 0];
                float v1 = acc[mi][ni][hh * 2 + 1];
                if (MODE == 2) {
                    if (n < Ncols)     Cf[(size_t)m * Ncols + n]     = v0 + bias[n];
                    if (n + 1 < Ncols) Cf[(size_t)m * Ncols + n + 1] = v1 + bias[n + 1];
                } else {
                    if (MODE == 0) {
                        v0 = fmaxf(v0 + bias[n], 0.f);
                        v1 = fmaxf(v1 + bias[n + 1], 0.f);
                    }
                    *(__half2*)(Oh + (size_t)m * Ncols + n) = __floats2half2_rn(v0, v1);
                }
            }
        }
    }
}

// ---------------- host orchestration ----------------
static inline void launch_gemm(int mode,
                               const __half* Aa, const __half* Bw,
                               __half* Oh, float* Cf, const float* bias,
                               int K, int Ncols, int Npad) {
    dim3 grid(Npad / BN, NNODES / BM);
    if (mode == 0) {
        cudaFuncSetAttribute(k_gemm_mma<0>, cudaFuncAttributeMaxDynamicSharedMemorySize, GEMM_SMEM);
        k_gemm_mma<0><<<grid, 512, GEMM_SMEM>>>(Aa, Bw, Oh, Cf, bias, K, Ncols, K / BKC);
    } else if (mode == 1) {
        cudaFuncSetAttribute(k_gemm_mma<1>, cudaFuncAttributeMaxDynamicSharedMemorySize, GEMM_SMEM);
        k_gemm_mma<1><<<grid, 512, GEMM_SMEM>>>(Aa, Bw, Oh, Cf, bias, K, Ncols, K / BKC);
    } else {
        cudaFuncSetAttribute(k_gemm_mma<2>, cudaFuncAttributeMaxDynamicSharedMemorySize, GEMM_SMEM);
        k_gemm_mma<2><<<grid, 512, GEMM_SMEM>>>(Aa, Bw, Oh, Cf, bias, K, Ncols, K / BKC);
    }
}

static inline void launch_wconv(const float* W, __half* Wt, int K, int N, int Npad) {
    dim3 grid(K / 32, Npad / 32);
    k_wconv<<<grid, dim3(32, 8)>>>(W, Wt, K, N);
}

extern "C" void kernel_launch(void* const* d_in, const int* in_sizes, int n_in,
                              void* d_out, int out_size) {
    const float* x    = (const float*)d_in[0];
    const int*   esrc = (const int*)d_in[1];
    const int*   edst = (const int*)d_in[2];
    const float* ew   = (const float*)d_in[3];
    const float* W1 = (const float*)d_in[4];
    const float* b1 = (const float*)d_in[5];
    const float* W2 = (const float*)d_in[6];
    const float* b2 = (const float*)d_in[7];
    const float* W3 = (const float*)d_in[8];
    const float* b3 = (const float*)d_in[9];
    const float* W4 = (const float*)d_in[10];
    const float* b4 = (const float*)d_in[11];
    const float* Wout = (const float*)d_in[12];
    const float* bout = (const float*)d_in[13];
    float* out = (float*)d_out;

    __half *abuf, *gbuf, *wt;
    cudaGetSymbolAddress((void**)&abuf, g_a);
    cudaGetSymbolAddress((void**)&gbuf, g_g);
    cudaGetSymbolAddress((void**)&wt, g_wt);

    // graph prep
    k_prep_zero<<<NNODES / 256, 256>>>();
    k_prep_edges<<<NEDGES / 256, 256>>>(esrc, edst, ew);
    k_scan<<<1, 1024>>>();
    k_fill<<<NEDGES / 256, 256>>>(esrc, edst, ew);

    // L1: g = agg(x) [512]; a = relu(g W1 + b1) [1024]
    {
        dim3 grid((512 / 4 + 127) / 128, NNODES);
        k_agg<0><<<grid, 128>>>(x, nullptr, nullptr, gbuf, 512);
    }
    launch_wconv(W1, wt, 512, 1024, 1024);
    launch_gemm(0, gbuf, wt, abuf, nullptr, b1, 512, 1024, 1024);

    // L2: g = agg(a) [1024]; a = relu(g W2 + b2) [2048]
    {
        dim3 grid((1024 / 8 + 127) / 128, NNODES);
        k_agg<1><<<grid, 128>>>(nullptr, abuf, nullptr, gbuf, 1024);
    }
    launch_wconv(W2, wt, 1024, 2048, 2048);
    launch_gemm(0, gbuf, wt, abuf, nullptr, b2, 1024, 2048, 2048);

    // L3: g = agg(a) [2048]; a = relu(g W3 + b3) [4096]
    {
        dim3 grid((2048 / 8 + 127) / 128, NNODES);
        k_agg<1><<<grid, 128>>>(nullptr, abuf, nullptr, gbuf, 2048);
    }
    launch_wconv(W3, wt, 2048, 4096, 4096);
    launch_gemm(0, gbuf, wt, abuf, nullptr, b3, 2048, 4096, 4096);

    // L4 (agg after): h = a W4 [2048]; a = relu(agg(h) + b4)
    launch_wconv(W4, wt, 4096, 2048, 2048);
    launch_gemm(1, abuf, wt, gbuf, nullptr, nullptr, 4096, 2048, 2048);
    {
        dim3 grid((2048 / 8 + 127) / 128, NNODES);
        k_agg<2><<<grid, 128>>>(nullptr, gbuf, b4, abuf, 2048);
    }

    // L5 (output): out = a Wout + bout [1000]
    launch_wconv(Wout, wt, 2048, 1000, 1024);
    launch_gemm(2, abuf, wt, nullptr, out, bout, 2048, 1000, 1024);
}

// round 17
// speedup vs baseline: 1.1506x; 1.0179x over previous
#include <cuda_runtime.h>
#include <cuda_fp16.h>
#include <cstdint>

#define NNODES 16384
#define NEDGES 65536
#define MAXF   4096

// ---------------- scratch (device globals; no allocation) ----------------
__device__ __half g_a[(size_t)NNODES * MAXF];     // activation buffer A (fp16)
__device__ __half g_g[(size_t)NNODES * MAXF];     // buffer B (fp16)
__device__ __half g_w1[(size_t)1024 * 512];       // per-layer transposed fp16 weights [Npad,K]
__device__ __half g_w2[(size_t)2048 * 1024];
__device__ __half g_w3[(size_t)4096 * 2048];
__device__ __half g_w4[(size_t)2048 * 4096];
__device__ __half g_w5[(size_t)1024 * 2048];
__device__ float g_deg[NNODES];
__device__ float g_dinv[NNODES];
__device__ float g_self[NNODES];
__device__ int   g_count[NNODES];
__device__ int   g_rowptr[NNODES + 1];
__device__ int   g_cursor[NNODES];
__device__ int   g_csrc[NEDGES];
__device__ float g_cw[NEDGES];

// ---------------- PTX helpers (baseline PTX only) ----------------
__device__ __forceinline__ uint32_t smem_u32(const void* p) {
    uint32_t a;
    asm("{ .reg .u64 t; cvta.to.shared.u64 t, %1; cvt.u32.u64 %0, t; }" : "=r"(a) : "l"(p));
    return a;
}
__device__ __forceinline__ void cp16(uint32_t s, const void* g) {
    asm volatile("cp.async.cg.shared.global [%0], [%1], 16;" :: "r"(s), "l"(g));
}
__device__ __forceinline__ void cp_commit() { asm volatile("cp.async.commit_group;" ::: "memory"); }
template <int N>
__device__ __forceinline__ void cp_wait() { asm volatile("cp.async.wait_group %0;" :: "n"(N) : "memory"); }

__device__ __forceinline__ void ldsm4(uint32_t* r, uint32_t addr) {
    asm volatile("ldmatrix.sync.aligned.m8n8.x4.shared.b16 {%0,%1,%2,%3}, [%4];"
                 : "=r"(r[0]), "=r"(r[1]), "=r"(r[2]), "=r"(r[3]) : "r"(addr));
}
__device__ __forceinline__ void mma16816(float* d, const uint32_t* a, const uint32_t* b) {
    asm volatile(
        "mma.sync.aligned.m16n8k16.row.col.f32.f16.f16.f32 "
        "{%0,%1,%2,%3}, {%4,%5,%6,%7}, {%8,%9}, {%0,%1,%2,%3};"
        : "+f"(d[0]), "+f"(d[1]), "+f"(d[2]), "+f"(d[3])
        : "r"(a[0]), "r"(a[1]), "r"(a[2]), "r"(a[3]), "r"(b[0]), "r"(b[1]));
}

// ---------------- graph prep ----------------
__global__ void k_prep_zero() {
    int i = blockIdx.x * blockDim.x + threadIdx.x;
    if (i < NNODES) { g_deg[i] = 0.f; g_count[i] = 0; }
}
__global__ void k_prep_edges(const int* __restrict__ src, const int* __restrict__ dst,
                             const float* __restrict__ ew) {
    int e = blockIdx.x * blockDim.x + threadIdx.x;
    if (e < NEDGES) {
        atomicAdd(&g_deg[dst[e]], ew[e]);
        atomicAdd(&g_count[dst[e]], 1);
    }
}
// single block, 1024 threads: node norms + exclusive scan of g_count (shfl-based)
__global__ void k_scan() {
    int tid = threadIdx.x;
    int lane = tid & 31, wid = tid >> 5;
#pragma unroll
    for (int j = 0; j < 16; j++) {
        int i = tid * 16 + j;
        float d = g_deg[i] + 1.0f;
        g_dinv[i] = rsqrtf(d);
        g_self[i] = 1.0f / d;
    }
    int c[16];
    int tot = 0;
#pragma unroll
    for (int j = 0; j < 16; j++) { c[j] = tot; tot += g_count[tid * 16 + j]; }

    // warp inclusive scan of tot
    unsigned mask = 0xffffffffu;
    int incl = tot;
#pragma unroll
    for (int off = 1; off < 32; off <<= 1) {
        int v = __shfl_up_sync(mask, incl, off);
        if (lane >= off) incl += v;
    }
    __shared__ int wsum[32];
    if (lane == 31) wsum[wid] = incl;
    __syncthreads();
    if (wid == 0) {
        int w = wsum[lane];
        int i2 = w;
#pragma unroll
        for (int off = 1; off < 32; off <<= 1) {
            int v = __shfl_up_sync(mask, i2, off);
            if (lane >= off) i2 += v;
        }
        wsum[lane] = i2 - w;   // exclusive warp base
    }
    __syncthreads();
    int base = wsum[wid];
    int excl = base + incl - tot;
#pragma unroll
    for (int j = 0; j < 16; j++) {
        int v = excl + c[j];
        g_rowptr[tid * 16 + j] = v;
        g_cursor[tid * 16 + j] = v;
    }
    if (tid == 1023) g_rowptr[NNODES] = base + incl;
}
__global__ void k_fill(const int* __restrict__ src, const int* __restrict__ dst,
                       const float* __restrict__ ew) {
    int e = blockIdx.x * blockDim.x + threadIdx.x;
    if (e < NEDGES) {
        int s = src[e], d = dst[e];
        float norm = g_dinv[s] * ew[e] * g_dinv[d];
        int p = atomicAdd(&g_cursor[d], 1);
        g_csrc[p] = s;
        g_cw[p] = norm;
    }
}

// ---------------- weight conversion: W [K,N] f32 -> Wt fp16 [Npad,K] ----------------
__global__ void k_wconv(const float* __restrict__ W, __half* __restrict__ Wt,
                        int K, int N) {
    __shared__ float t[32][33];
    int k0 = blockIdx.x * 32, nb0 = blockIdx.y * 32;
    int tx = threadIdx.x, ty = threadIdx.y;
    for (int r = ty; r < 32; r += 8) {
        int nn = nb0 + tx;
        t[r][tx] = (nn < N) ? W[(size_t)(k0 + r) * N + nn] : 0.f;
    }
    __syncthreads();
    for (int r = ty; r < 32; r += 8) {
        int nn = nb0 + r;
        Wt[(size_t)nn * K + k0 + tx] = __float2half(t[tx][r]);
    }
}

// ---------------- aggregation kernels (CSR gather, 16B vectorized) ----------------
// MODE 0: f32 input (layer 1, x); MODE 1: fp16 input; MODE 2: fp16 + bias + relu
template <int MODE>
__global__ void k_agg(const float* __restrict__ xf, const __half* __restrict__ inA,
                      const float* __restrict__ bias,
                      __half* __restrict__ outA, int F) {
    int n = blockIdx.y;
    int v = blockIdx.x * blockDim.x + threadIdx.x;

    if (MODE == 0) {
        int F4 = F >> 2;
        if (v >= F4) return;
        const float4* base = (const float4*)xf;
        float sc = g_self[n];
        float4 hv = base[(size_t)n * F4 + v];
        float4 acc = make_float4(sc * hv.x, sc * hv.y, sc * hv.z, sc * hv.w);
        int beg = g_rowptr[n], end = g_rowptr[n + 1];
        for (int j = beg; j < end; j++) {
            int   s = g_csrc[j];
            float w = g_cw[j];
            float4 sv = base[(size_t)s * F4 + v];
            acc.x += w * sv.x; acc.y += w * sv.y;
            acc.z += w * sv.z; acc.w += w * sv.w;
        }
        union { uint2 u; __half2 h[2]; } o;
        o.h[0] = __floats2half2_rn(acc.x, acc.y);
        o.h[1] = __floats2half2_rn(acc.z, acc.w);
        ((uint2*)(outA + (size_t)n * F))[v] = o.u;
    } else {
        int F8 = F >> 3;
        if (v >= F8) return;
        const uint4* base = (const uint4*)inA;
        float sc = g_self[n];
        union { uint4 u; __half2 h[4]; } r;
        r.u = base[(size_t)n * F8 + v];
        float a[8];
#pragma unroll
        for (int q = 0; q < 4; q++) {
            float2 f = __half22float2(r.h[q]);
            a[2 * q + 0] = sc * f.x;
            a[2 * q + 1] = sc * f.y;
        }
        int beg = g_rowptr[n], end = g_rowptr[n + 1];
        for (int j = beg; j < end; j++) {
            int   s = g_csrc[j];
            float w = g_cw[j];
            union { uint4 u; __half2 h[4]; } rv;
            rv.u = base[(size_t)s * F8 + v];
#pragma unroll
            for (int q = 0; q < 4; q++) {
                float2 f = __half22float2(rv.h[q]);
                a[2 * q + 0] += w * f.x;
                a[2 * q + 1] += w * f.y;
            }
        }
        if (MODE == 2) {
            float4 b0 = ((const float4*)bias)[2 * v + 0];
            float4 b1 = ((const float4*)bias)[2 * v + 1];
            a[0] = fmaxf(a[0] + b0.x, 0.f); a[1] = fmaxf(a[1] + b0.y, 0.f);
            a[2] = fmaxf(a[2] + b0.z, 0.f); a[3] = fmaxf(a[3] + b0.w, 0.f);
            a[4] = fmaxf(a[4] + b1.x, 0.f); a[5] = fmaxf(a[5] + b1.y, 0.f);
            a[6] = fmaxf(a[6] + b1.z, 0.f); a[7] = fmaxf(a[7] + b1.w, 0.f);
        }
        union { uint4 u; __half2 h[4]; } o;
#pragma unroll
        for (int q = 0; q < 4; q++)
            o.h[q] = __floats2half2_rn(a[2 * q + 0], a[2 * q + 1]);
        ((uint4*)(outA + (size_t)n * F))[v] = o.u;
    }
}

// ---------------- mma.sync fp16 GEMM (single term, templated BN) ----------------
// CTA 128xBNT, 512 threads (16 warps, warp tile 32x(BNT/4)), BK=32, 4-stage cp.async.
#define BM 128
#define BKC 32
#define LDT 40                          // fp16 elems per row (80 B)
#define A_T (128 * LDT * 2)             // 10240 B
#define NSTAGE 4

template <int MODE, int BNT>
__global__ void __launch_bounds__(512, 1)
k_gemm_mma(const __half* __restrict__ Aa, const __half* __restrict__ Bw,
           __half* __restrict__ Oh, float* __restrict__ Cf,
           const float* __restrict__ bias,
           int K, int Ncols, int KC) {
    constexpr int B_T = BNT * LDT * 2;
    constexpr int STAGE_B = A_T + B_T;
    constexpr int WN = BNT / 4;       // warp n tile
    constexpr int FN = WN / 8;        // n-frags per warp

    extern __shared__ char smem[];
    uint32_t sb = smem_u32(smem);
    int tid = threadIdx.x;
    int wid = tid >> 5, lane = tid & 31;
    int m0 = blockIdx.y * BM, n0 = blockIdx.x * BNT;
    int wm = wid & 3;
    int wn = wid >> 2;

    const __half* A0 = Aa + (size_t)m0 * K;
    const __half* B0 = Bw + (size_t)n0 * K;

    int lrow = tid >> 2;       // 0..127
    int lg   = tid & 3;        // 16B group
    auto load_chunk = [&](int c, int s) {
        uint32_t tb = sb + s * STAGE_B;
        size_t koff = (size_t)c * BKC;
        cp16(tb + (uint32_t)(lrow * (LDT * 2) + lg * 16),
             A0 + (size_t)lrow * K + koff + lg * 8);
#pragma unroll
        for (int i = tid; i < BNT * 4; i += 512) {
            int row = i >> 2, g = i & 3;
            cp16(tb + A_T + (uint32_t)(row * (LDT * 2) + g * 16),
                 B0 + (size_t)row * K + koff + g * 8);
        }
    };

    int quad = lane >> 3, r = lane & 7;
    uint32_t aOff = (uint32_t)(((wm * 32 + (quad & 1) * 8 + r) * LDT + (quad >> 1) * 8) * 2);
    uint32_t bOff = (uint32_t)(((wn * WN + (quad >> 1) * 8 + r) * LDT + (quad & 1) * 8) * 2);

    float acc[2][FN][4];
#pragma unroll
    for (int i = 0; i < 2; i++)
#pragma unroll
        for (int j = 0; j < FN; j++)
#pragma unroll
            for (int q = 0; q < 4; q++) acc[i][j][q] = 0.f;

    load_chunk(0, 0); cp_commit();
    if (KC > 1) { load_chunk(1, 1); cp_commit(); }
    if (KC > 2) { load_chunk(2, 2); cp_commit(); }

    for (int kc = 0; kc < KC; kc++) {
        int s = kc & 3;
        int after = (kc + 3 < KC ? 3 : KC - 1 - kc);
        if (after >= 2) cp_wait<2>();
        else if (after == 1) cp_wait<1>();
        else cp_wait<0>();
        __syncthreads();

        uint32_t st = sb + s * STAGE_B;
#pragma unroll
        for (int ks = 0; ks < 2; ks++) {
            uint32_t ko = ks * 32;
            uint32_t af[2][4], bf[FN / 2][4];
#pragma unroll
            for (int mi = 0; mi < 2; mi++)
                ldsm4(af[mi], st + aOff + mi * (16 * LDT * 2) + ko);
#pragma unroll
            for (int p = 0; p < FN / 2; p++)
                ldsm4(bf[p], st + A_T + bOff + p * (16 * LDT * 2) + ko);
#pragma unroll
            for (int p = 0; p < FN / 2; p++)
#pragma unroll
                for (int mi = 0; mi < 2; mi++)
#pragma unroll
                    for (int h = 0; h < 2; h++)
                        mma16816(acc[mi][2 * p + h], af[mi], &bf[p][h * 2]);
        }

        if (kc + 3 < KC) {
            load_chunk(kc + 3, (kc + 3) & 3);
            cp_commit();
        }
        __syncthreads();
    }

    // epilogue
    int cr = lane >> 2, cc = (lane & 3) * 2;
#pragma unroll
    for (int mi = 0; mi < 2; mi++) {
#pragma unroll
        for (int ni = 0; ni < FN; ni++) {
            int n = n0 + wn * WN + ni * 8 + cc;
#pragma unroll
            for (int hh = 0; hh < 2; hh++) {
                int m = m0 + wm * 32 + mi * 16 + cr + hh * 8;
                float v0 = acc[mi][ni][hh * 2 + 0];
                float v1 = acc[mi][ni][hh * 2 + 1];
                if (MODE == 2) {
                    if (n < Ncols)     Cf[(size_t)m * Ncols + n]     = v0 + bias[n];
                    if (n + 1 < Ncols) Cf[(size_t)m * Ncols + n + 1] = v1 + bias[n + 1];
                } else {
                    if (MODE == 0) {
                        v0 = fmaxf(v0 + bias[n], 0.f);
                        v1 = fmaxf(v1 + bias[n + 1], 0.f);
                    }
                    *(__half2*)(Oh + (size_t)m * Ncols + n) = __floats2half2_rn(v0, v1);
                }
            }
        }
    }
}

// ---------------- host orchestration ----------------
template <int MODE, int BNT>
static inline void do_gemm(const __half* Aa, const __half* Bw,
                           __half* Oh, float* Cf, const float* bias,
                           int K, int Ncols, int Npad, cudaStream_t st) {
    constexpr int SMEM = NSTAGE * (A_T + BNT * LDT * 2);
    cudaFuncSetAttribute(k_gemm_mma<MODE, BNT>, cudaFuncAttributeMaxDynamicSharedMemorySize, SMEM);
    dim3 grid(Npad / BNT, NNODES / BM);
    k_gemm_mma<MODE, BNT><<<grid, 512, SMEM, st>>>(Aa, Bw, Oh, Cf, bias, K, Ncols, K / BKC);
}

static inline void launch_wconv(const float* W, __half* Wt, int K, int N, int Npad,
                                cudaStream_t st) {
    dim3 grid(K / 32, Npad / 32);
    k_wconv<<<grid, dim3(32, 8), 0, st>>>(W, Wt, K, N);
}

extern "C" void kernel_launch(void* const* d_in, const int* in_sizes, int n_in,
                              void* d_out, int out_size) {
    const float* x    = (const float*)d_in[0];
    const int*   esrc = (const int*)d_in[1];
    const int*   edst = (const int*)d_in[2];
    const float* ew   = (const float*)d_in[3];
    const float* W1 = (const float*)d_in[4];
    const float* b1 = (const float*)d_in[5];
    const float* W2 = (const float*)d_in[6];
    const float* b2 = (const float*)d_in[7];
    const float* W3 = (const float*)d_in[8];
    const float* b3 = (const float*)d_in[9];
    const float* W4 = (const float*)d_in[10];
    const float* b4 = (const float*)d_in[11];
    const float* Wout = (const float*)d_in[12];
    const float* bout = (const float*)d_in[13];
    float* out = (float*)d_out;

    __half *abuf, *gbuf, *w1, *w2, *w3, *w4, *w5;
    cudaGetSymbolAddress((void**)&abuf, g_a);
    cudaGetSymbolAddress((void**)&gbuf, g_g);
    cudaGetSymbolAddress((void**)&w1, g_w1);
    cudaGetSymbolAddress((void**)&w2, g_w2);
    cudaGetSymbolAddress((void**)&w3, g_w3);
    cudaGetSymbolAddress((void**)&w4, g_w4);
    cudaGetSymbolAddress((void**)&w5, g_w5);

    cudaStream_t s0 = (cudaStream_t)0;

    // try to fork a side stream for weight conversion (overlap with main chain)
    cudaStream_t s2 = nullptr;
    cudaEvent_t evFork = nullptr, evW[5] = {};
    bool use2 = (cudaStreamCreateWithFlags(&s2, cudaStreamNonBlocking) == cudaSuccess);
    if (use2) {
        if (cudaEventCreateWithFlags(&evFork, cudaEventDisableTiming) != cudaSuccess) use2 = false;
        for (int i = 0; use2 && i < 5; i++)
            if (cudaEventCreateWithFlags(&evW[i], cudaEventDisableTiming) != cudaSuccess) use2 = false;
    }

    cudaStream_t ws = use2 ? s2 : s0;
    if (use2) {
        cudaEventRecord(evFork, s0);
        cudaStreamWaitEvent(s2, evFork, 0);
    }
    // weight conversions (side stream if available)
    launch_wconv(W1,   w1, 512,  1024, 1024, ws);
    if (use2) cudaEventRecord(evW[0], s2);
    launch_wconv(W2,   w2, 1024, 2048, 2048, ws);
    if (use2) cudaEventRecord(evW[1], s2);
    launch_wconv(W3,   w3, 2048, 4096, 4096, ws);
    if (use2) cudaEventRecord(evW[2], s2);
    launch_wconv(W4,   w4, 4096, 2048, 2048, ws);
    if (use2) cudaEventRecord(evW[3], s2);
    launch_wconv(Wout, w5, 2048, 1000, 1024, ws);
    if (use2) cudaEventRecord(evW[4], s2);

    // graph prep (main chain)
    k_prep_zero<<<NNODES / 256, 256>>>();
    k_prep_edges<<<NEDGES / 256, 256>>>(esrc, edst, ew);
    k_scan<<<1, 1024>>>();
    k_fill<<<NEDGES / 256, 256>>>(esrc, edst, ew);

    // L1: g = agg(x) [512]; a = relu(g W1 + b1) [1024]
    {
        dim3 grid((512 / 4 + 127) / 128, NNODES);
        k_agg<0><<<grid, 128>>>(x, nullptr, nullptr, gbuf, 512);
    }
    if (use2) cudaStreamWaitEvent(s0, evW[0], 0);
    do_gemm<0, 256>(gbuf, w1, abuf, nullptr, b1, 512, 1024, 1024, s0);

    // L2
    {
        dim3 grid((1024 / 8 + 127) / 128, NNODES);
        k_agg<1><<<grid, 128>>>(nullptr, abuf, nullptr, gbuf, 1024);
    }
    if (use2) cudaStreamWaitEvent(s0, evW[1], 0);
    do_gemm<0, 256>(gbuf, w2, abuf, nullptr, b2, 1024, 2048, 2048, s0);

    // L3
    {
        dim3 grid((2048 / 8 + 127) / 128, NNODES);
        k_agg<1><<<grid, 128>>>(nullptr, abuf, nullptr, gbuf, 2048);
    }
    if (use2) cudaStreamWaitEvent(s0, evW[2], 0);
    do_gemm<0, 256>(gbuf, w3, abuf, nullptr, b3, 2048, 4096, 4096, s0);

    // L4 (agg after)
    if (use2) cudaStreamWaitEvent(s0, evW[3], 0);
    do_gemm<1, 256>(abuf, w4, gbuf, nullptr, nullptr, 4096, 2048, 2048, s0);
    {
        dim3 grid((2048 / 8 + 127) / 128, NNODES);
        k_agg<2><<<grid, 128>>>(nullptr, gbuf, b4, abuf, 2048);
    }

    // L5 (output): BN=128 variant for better wave quantization
    if (use2) cudaStreamWaitEvent(s0, evW[4], 0);
    do_gemm<2, 128>(abuf, w5, nullptr, out, bout, 2048, 1000, 1024, s0);

    // NOTE: s2/events intentionally not destroyed here — kernel_launch is called
    // only a handful of times (correctness + capture); destroying a forked stream
    // mid-capture can invalidate the graph. Host-side resources only.
}